// round 2
// baseline (speedup 1.0000x reference)
#include <cuda_runtime.h>
#include <cuda_bf16.h>
#include <cstdint>

#define N_NODES 50000
#define N_EDGES 800000
#define DD      128
#define RTILE   32
#define BN_EPS  1e-5f

// ---------------- scratch (device globals; no cudaMalloc allowed) ----------
__device__ float g_S[(size_t)N_NODES * DD];     // self-path GEMM output
__device__ float g_P[(size_t)N_NODES * DD];     // neigh-path GEMM output
__device__ float g_H[(size_t)N_NODES * DD];     // layer activations (pre-BN)
__device__ int   g_deg[N_NODES];
__device__ int   g_rowptr[N_NODES + 1];
__device__ int   g_cursor[N_NODES];
__device__ int   g_csr[N_EDGES];
__device__ float g_colstats[2 * DD];            // [0:128) colsum, [128:256) colsumsq

// ---------------- f32x2 helpers (sm_103a packed fp32) ----------------------
__device__ __forceinline__ unsigned long long pack2(float a, float b) {
    unsigned long long r;
    asm("mov.b64 %0, {%1, %2};" : "=l"(r) : "f"(a), "f"(b));
    return r;
}
__device__ __forceinline__ void fma2(unsigned long long& d,
                                     unsigned long long a,
                                     unsigned long long b) {
    asm("fma.rn.f32x2 %0, %1, %2, %0;" : "+l"(d) : "l"(a), "l"(b));
}
__device__ __forceinline__ float unpack_sum(unsigned long long v) {
    float lo, hi;
    asm("mov.b64 {%0, %1}, %2;" : "=f"(lo), "=f"(hi) : "l"(v));
    return lo + hi;
}

// ---------------- CSR build -------------------------------------------------
__global__ void k_hist(const int* __restrict__ dst, int* __restrict__ deg) {
    int e = blockIdx.x * blockDim.x + threadIdx.x;
    if (e < N_EDGES) atomicAdd(&deg[dst[e]], 1);
}

__global__ void k_scan(const int* __restrict__ deg, int* __restrict__ rowptr) {
    __shared__ int sh[1024];
    int carry = 0;
    if (threadIdx.x == 0) rowptr[0] = 0;
    for (int base = 0; base < N_NODES; base += 1024) {
        int i = base + threadIdx.x;
        int v = (i < N_NODES) ? deg[i] : 0;
        sh[threadIdx.x] = v;
        __syncthreads();
        for (int off = 1; off < 1024; off <<= 1) {
            int t = (threadIdx.x >= off) ? sh[threadIdx.x - off] : 0;
            __syncthreads();
            sh[threadIdx.x] += t;
            __syncthreads();
        }
        if (i < N_NODES) rowptr[i + 1] = carry + sh[threadIdx.x];
        carry += sh[1023];
        __syncthreads();
    }
}

__global__ void k_fill(const int* __restrict__ src, const int* __restrict__ dst,
                       int* __restrict__ cursor, int* __restrict__ csr) {
    int e = blockIdx.x * blockDim.x + threadIdx.x;
    if (e < N_EDGES) {
        int d = dst[e];
        int p = atomicAdd(&cursor[d], 1);
        csr[p] = src[e];
    }
}

// ---------------- fused dual GEMM: S = bn(H)@Wself + b, P = bn(H)@Wneigh ----
// 256 threads: thread c in [0,256) owns one output column (c<128 -> Wself,
// else Wneigh col c-128). RTILE rows per block, activation tile staged in smem
// with BN+ReLU applied at load. Inner product packed along K via fma.rn.f32x2.
__global__ __launch_bounds__(256)
void k_gemm_dual(const float* __restrict__ H,
                 const float* __restrict__ Wself,
                 const float* __restrict__ Wneigh,
                 const float* __restrict__ bias,
                 const float* __restrict__ colstats,  // null -> no BN/ReLU
                 const float* __restrict__ gamma,
                 const float* __restrict__ beta,
                 float* __restrict__ S,
                 float* __restrict__ P) {
    __shared__ float Hs[RTILE][DD];
    __shared__ float s_scale[DD];
    __shared__ float s_shift[DD];

    const int tid = threadIdx.x;
    const int row0 = blockIdx.x * RTILE;
    const bool useBn = (colstats != nullptr);

    if (tid < DD) {
        float scale = 1.0f, shift = 0.0f;
        if (useBn) {
            float m   = colstats[tid] * (1.0f / N_NODES);
            float var = colstats[DD + tid] * (1.0f / N_NODES) - m * m;
            float rs  = rsqrtf(var + BN_EPS);
            scale = rs * gamma[tid];
            shift = beta[tid] - m * scale;
        }
        s_scale[tid] = scale;
        s_shift[tid] = shift;
    }
    __syncthreads();

    int nrows = N_NODES - row0;
    if (nrows > RTILE) nrows = RTILE;

    // load tile (coalesced float4), apply BN(+ReLU) elementwise
#pragma unroll
    for (int i = 0; i < 4; i++) {
        int f  = tid + i * 256;         // float4 id, 1024 total
        int r  = f >> 5;                // row within tile
        int k4 = f & 31;                // float4 column
        float4 v = make_float4(0.f, 0.f, 0.f, 0.f);
        if (r < nrows)
            v = *(const float4*)(H + (size_t)(row0 + r) * DD + k4 * 4);
        int k = k4 * 4;
        float x0, x1, x2, x3;
        if (useBn) {
            x0 = fmaxf(v.x * s_scale[k + 0] + s_shift[k + 0], 0.f);
            x1 = fmaxf(v.y * s_scale[k + 1] + s_shift[k + 1], 0.f);
            x2 = fmaxf(v.z * s_scale[k + 2] + s_shift[k + 2], 0.f);
            x3 = fmaxf(v.w * s_scale[k + 3] + s_shift[k + 3], 0.f);
        } else {
            x0 = v.x; x1 = v.y; x2 = v.z; x3 = v.w;
        }
        Hs[r][k + 0] = x0;
        Hs[r][k + 1] = x1;
        Hs[r][k + 2] = x2;
        Hs[r][k + 3] = x3;
    }
    __syncthreads();

    const int c = tid;                                 // output column 0..255
    const float* Wcol = (c < DD) ? (Wself + c) : (Wneigh + (c - DD));

    unsigned long long acc[RTILE];
#pragma unroll
    for (int r = 0; r < RTILE; r++) acc[r] = 0ULL;

    for (int k = 0; k < DD; k += 8) {
        float w0 = __ldg(&Wcol[(k + 0) * DD]);
        float w1 = __ldg(&Wcol[(k + 1) * DD]);
        float w2 = __ldg(&Wcol[(k + 2) * DD]);
        float w3 = __ldg(&Wcol[(k + 3) * DD]);
        float w4 = __ldg(&Wcol[(k + 4) * DD]);
        float w5 = __ldg(&Wcol[(k + 5) * DD]);
        float w6 = __ldg(&Wcol[(k + 6) * DD]);
        float w7 = __ldg(&Wcol[(k + 7) * DD]);
        unsigned long long wp0 = pack2(w0, w1);
        unsigned long long wp1 = pack2(w2, w3);
        unsigned long long wp2 = pack2(w4, w5);
        unsigned long long wp3 = pack2(w6, w7);
#pragma unroll
        for (int r = 0; r < RTILE; r++) {
            const ulonglong2* hpA = (const ulonglong2*)&Hs[r][k];
            ulonglong2 a = hpA[0];   // (k,k+1),(k+2,k+3)
            ulonglong2 b = hpA[1];   // (k+4,k+5),(k+6,k+7)
            fma2(acc[r], a.x, wp0);
            fma2(acc[r], a.y, wp1);
            fma2(acc[r], b.x, wp2);
            fma2(acc[r], b.y, wp3);
        }
    }

    const float bval = (c < DD) ? __ldg(&bias[c]) : 0.0f;
#pragma unroll
    for (int r = 0; r < RTILE; r++) {
        if (r < nrows) {
            float res = unpack_sum(acc[r]) + bval;
            size_t rowoff = (size_t)(row0 + r) * DD;
            if (c < DD) S[rowoff + c] = res;
            else        P[rowoff + (c - DD)] = res;
        }
    }
}

// ---------------- pull-style aggregation: out = S + mean_neigh(P) -----------
__global__ __launch_bounds__(256)
void k_agg(const float* __restrict__ S, const float* __restrict__ P,
           const int* __restrict__ csr, const int* __restrict__ rowptr,
           float* __restrict__ out) {
    int warp = (blockIdx.x * blockDim.x + threadIdx.x) >> 5;
    int lane = threadIdx.x & 31;
    if (warp >= N_NODES) return;

    int beg = rowptr[warp];
    int end = rowptr[warp + 1];

    float4 acc = make_float4(0.f, 0.f, 0.f, 0.f);
    int e = beg;
#pragma unroll 1
    for (; e + 1 < end; e += 2) {
        int s0 = __ldg(&csr[e]);
        int s1 = __ldg(&csr[e + 1]);
        float4 p0 = *(const float4*)(P + (size_t)s0 * DD + lane * 4);
        float4 p1 = *(const float4*)(P + (size_t)s1 * DD + lane * 4);
        acc.x += p0.x + p1.x;
        acc.y += p0.y + p1.y;
        acc.z += p0.z + p1.z;
        acc.w += p0.w + p1.w;
    }
    if (e < end) {
        int s0 = __ldg(&csr[e]);
        float4 p0 = *(const float4*)(P + (size_t)s0 * DD + lane * 4);
        acc.x += p0.x; acc.y += p0.y; acc.z += p0.z; acc.w += p0.w;
    }

    float inv = 1.0f / fmaxf((float)(end - beg), 1.0f);
    float4 s4 = *(const float4*)(S + (size_t)warp * DD + lane * 4);
    float4 o;
    o.x = s4.x + acc.x * inv;
    o.y = s4.y + acc.y * inv;
    o.z = s4.z + acc.z * inv;
    o.w = s4.w + acc.w * inv;
    *(float4*)(out + (size_t)warp * DD + lane * 4) = o;
}

// ---------------- BN statistics (column sum / sumsq) ------------------------
__global__ __launch_bounds__(128)
void k_bnstats(const float* __restrict__ H, float* __restrict__ colstats) {
    int c = threadIdx.x;   // 128 threads, one column each
    float s = 0.f, ss = 0.f;
    for (int r = blockIdx.x; r < N_NODES; r += gridDim.x) {
        float v = H[(size_t)r * DD + c];
        s  += v;
        ss += v * v;
    }
    atomicAdd(&colstats[c], s);
    atomicAdd(&colstats[DD + c], ss);
}

// ---------------- launch ----------------------------------------------------
extern "C" void kernel_launch(void* const* d_in, const int* in_sizes, int n_in,
                              void* d_out, int out_size) {
    const float* x       = (const float*)d_in[0];
    const int*   src     = (const int*)d_in[1];
    const int*   dst     = (const int*)d_in[2];
    const float* Wself0  = (const float*)d_in[3];
    const float* Wneigh0 = (const float*)d_in[4];
    const float* b0      = (const float*)d_in[5];
    const float* Wself1  = (const float*)d_in[6];
    const float* Wneigh1 = (const float*)d_in[7];
    const float* b1      = (const float*)d_in[8];
    const float* Wself2  = (const float*)d_in[9];
    const float* Wneigh2 = (const float*)d_in[10];
    const float* b2      = (const float*)d_in[11];
    const float* gamma0  = (const float*)d_in[12];
    const float* beta0   = (const float*)d_in[13];
    const float* gamma1  = (const float*)d_in[14];
    const float* beta1   = (const float*)d_in[15];
    float* out = (float*)d_out;

    float *pS, *pP, *pH, *pstats;
    int *pdeg, *prowptr, *pcursor, *pcsr;
    cudaGetSymbolAddress((void**)&pS, g_S);
    cudaGetSymbolAddress((void**)&pP, g_P);
    cudaGetSymbolAddress((void**)&pH, g_H);
    cudaGetSymbolAddress((void**)&pstats, g_colstats);
    cudaGetSymbolAddress((void**)&pdeg, g_deg);
    cudaGetSymbolAddress((void**)&prowptr, g_rowptr);
    cudaGetSymbolAddress((void**)&pcursor, g_cursor);
    cudaGetSymbolAddress((void**)&pcsr, g_csr);

    const int TPB = 256;
    const int edgeBlocks = (N_EDGES + TPB - 1) / TPB;
    const int gemmBlocks = (N_NODES + RTILE - 1) / RTILE;
    const int aggBlocks  = (N_NODES * 32 + TPB - 1) / TPB;

    // ---- CSR build (shared by all 3 layers) ----
    cudaMemsetAsync(pdeg, 0, N_NODES * sizeof(int));
    k_hist<<<edgeBlocks, TPB>>>(dst, pdeg);
    k_scan<<<1, 1024>>>(pdeg, prowptr);
    cudaMemcpyAsync(pcursor, prowptr, N_NODES * sizeof(int),
                    cudaMemcpyDeviceToDevice);
    k_fill<<<edgeBlocks, TPB>>>(src, dst, pcursor, pcsr);

    // ---- layer 0: input x, no BN ----
    k_gemm_dual<<<gemmBlocks, TPB>>>(x, Wself0, Wneigh0, b0,
                                     nullptr, nullptr, nullptr, pS, pP);
    k_agg<<<aggBlocks, TPB>>>(pS, pP, pcsr, prowptr, pH);
    cudaMemsetAsync(pstats, 0, 2 * DD * sizeof(float));
    k_bnstats<<<240, 128>>>(pH, pstats);

    // ---- layer 1: BN(gamma0,beta0)+ReLU fused into GEMM load ----
    k_gemm_dual<<<gemmBlocks, TPB>>>(pH, Wself1, Wneigh1, b1,
                                     pstats, gamma0, beta0, pS, pP);
    k_agg<<<aggBlocks, TPB>>>(pS, pP, pcsr, prowptr, pH);
    cudaMemsetAsync(pstats, 0, 2 * DD * sizeof(float));
    k_bnstats<<<240, 128>>>(pH, pstats);

    // ---- layer 2: BN(gamma1,beta1)+ReLU fused, aggregate into d_out ----
    k_gemm_dual<<<gemmBlocks, TPB>>>(pH, Wself2, Wneigh2, b2,
                                     pstats, gamma1, beta1, pS, pP);
    k_agg<<<aggBlocks, TPB>>>(pS, pP, pcsr, prowptr, out);
}

// round 6
// speedup vs baseline: 1.2490x; 1.2490x over previous
#include <cuda_runtime.h>
#include <cuda_bf16.h>
#include <cstdint>

#define N_NODES 50000
#define N_EDGES 800000
#define DD      128
#define RTILE   32
#define BN_EPS  1e-5f
#define SCAN_T  512
#define SCAN_B  ((N_NODES + SCAN_T - 1) / SCAN_T)   // 98

// ---------------- scratch (device globals; no cudaMalloc allowed) ----------
__device__ float g_S[(size_t)N_NODES * DD];     // self-path GEMM output
__device__ float g_P[(size_t)N_NODES * DD];     // neigh-path GEMM output
__device__ float g_H[(size_t)N_NODES * DD];     // layer activations (pre-BN)
__device__ int   g_deg[N_NODES];
__device__ int   g_rowptr[N_NODES + 1];
__device__ int   g_cursor[N_NODES];
__device__ int   g_csr[N_EDGES];
__device__ int   g_bsum[128];
__device__ float g_colstats[2 * DD];            // [0:128) colsum, [128:256) colsumsq

// ---------------- f32x2 helpers (sm_103a packed fp32) ----------------------
__device__ __forceinline__ unsigned long long pack2(float a, float b) {
    unsigned long long r;
    asm("mov.b64 %0, {%1, %2};" : "=l"(r) : "f"(a), "f"(b));
    return r;
}
__device__ __forceinline__ void fma2(unsigned long long& d,
                                     unsigned long long a,
                                     unsigned long long b) {
    asm("fma.rn.f32x2 %0, %1, %2, %0;" : "+l"(d) : "l"(a), "l"(b));
}
__device__ __forceinline__ float unpack_sum(unsigned long long v) {
    float lo, hi;
    asm("mov.b64 {%0, %1}, %2;" : "=f"(lo), "=f"(hi) : "l"(v));
    return lo + hi;
}

// ---------------- CSR build -------------------------------------------------
__global__ void k_hist(const int* __restrict__ dst, int* __restrict__ deg) {
    int e = blockIdx.x * blockDim.x + threadIdx.x;
    if (e < N_EDGES) atomicAdd(&deg[dst[e]], 1);
}

// hierarchical scan: phase 1 — per-block inclusive scan + block sums
__global__ __launch_bounds__(SCAN_T)
void k_scan_part(const int* __restrict__ deg, int* __restrict__ rowptr,
                 int* __restrict__ bsum) {
    __shared__ int sh[SCAN_T];
    int t = threadIdx.x;
    int i = blockIdx.x * SCAN_T + t;
    int v = (i < N_NODES) ? deg[i] : 0;
    sh[t] = v;
    __syncthreads();
#pragma unroll
    for (int off = 1; off < SCAN_T; off <<= 1) {
        int u = (t >= off) ? sh[t - off] : 0;
        __syncthreads();
        sh[t] += u;
        __syncthreads();
    }
    if (i < N_NODES) rowptr[i + 1] = sh[t];
    if (t == SCAN_T - 1) bsum[blockIdx.x] = sh[t];
    if (i == 0) rowptr[0] = 0;
}

// phase 2 — scan the block sums (one block)
__global__ __launch_bounds__(128)
void k_scan_top(int* __restrict__ bsum) {
    __shared__ int sh[128];
    int t = threadIdx.x;
    int v = (t < SCAN_B) ? bsum[t] : 0;
    sh[t] = v;
    __syncthreads();
#pragma unroll
    for (int off = 1; off < 128; off <<= 1) {
        int u = (t >= off) ? sh[t - off] : 0;
        __syncthreads();
        sh[t] += u;
        __syncthreads();
    }
    if (t < SCAN_B) bsum[t] = sh[t];
}

// phase 3 — add block offsets
__global__ __launch_bounds__(SCAN_T)
void k_scan_add(int* __restrict__ rowptr, const int* __restrict__ bsum) {
    int b = blockIdx.x;
    if (b == 0) return;
    int i = b * SCAN_T + threadIdx.x;
    if (i < N_NODES) rowptr[i + 1] += bsum[b - 1];
}

__global__ void k_fill(const int* __restrict__ src, const int* __restrict__ dst,
                       int* __restrict__ cursor, int* __restrict__ csr) {
    int e = blockIdx.x * blockDim.x + threadIdx.x;
    if (e < N_EDGES) {
        int d = dst[e];
        int p = atomicAdd(&cursor[d], 1);
        csr[p] = src[e];
    }
}

// ---------------- fused dual GEMM: S = bn(H)@Wself + b, P = bn(H)@Wneigh ----
// 256 threads; thread (c = tid&127, rg = tid>>7) computes BOTH output columns
// (Wself col c AND Wneigh col c) for 16 rows of the 32-row tile (row group rg).
// This doubles FMAs per shared-memory wavefront vs. one-column-per-thread:
// per warp per 8-K step: 32 LDS.128 broadcast wavefronts vs 128 FFMA2 -> FMA bound.
__global__ __launch_bounds__(256, 2)
void k_gemm_dual(const float* __restrict__ H,
                 const float* __restrict__ Wself,
                 const float* __restrict__ Wneigh,
                 const float* __restrict__ bias,
                 const float* __restrict__ colstats,  // null -> no BN/ReLU
                 const float* __restrict__ gamma,
                 const float* __restrict__ beta,
                 float* __restrict__ S,
                 float* __restrict__ P) {
    __shared__ float Hs[RTILE][DD];
    __shared__ float s_scale[DD];
    __shared__ float s_shift[DD];

    const int tid = threadIdx.x;
    const int row0 = blockIdx.x * RTILE;
    const bool useBn = (colstats != nullptr);

    if (tid < DD) {
        float scale = 1.0f, shift = 0.0f;
        if (useBn) {
            float m   = colstats[tid] * (1.0f / N_NODES);
            float var = colstats[DD + tid] * (1.0f / N_NODES) - m * m;
            float rs  = rsqrtf(var + BN_EPS);
            scale = rs * gamma[tid];
            shift = beta[tid] - m * scale;
        }
        s_scale[tid] = scale;
        s_shift[tid] = shift;
    }
    __syncthreads();

    int nrows = N_NODES - row0;
    if (nrows > RTILE) nrows = RTILE;

    // load tile (coalesced float4), apply BN(+ReLU) elementwise
#pragma unroll
    for (int i = 0; i < 4; i++) {
        int f  = tid + i * 256;         // float4 id, 1024 total
        int r  = f >> 5;                // row within tile
        int k4 = f & 31;                // float4 column
        float4 v = make_float4(0.f, 0.f, 0.f, 0.f);
        if (r < nrows)
            v = *(const float4*)(H + (size_t)(row0 + r) * DD + k4 * 4);
        int k = k4 * 4;
        float x0, x1, x2, x3;
        if (useBn) {
            x0 = fmaxf(v.x * s_scale[k + 0] + s_shift[k + 0], 0.f);
            x1 = fmaxf(v.y * s_scale[k + 1] + s_shift[k + 1], 0.f);
            x2 = fmaxf(v.z * s_scale[k + 2] + s_shift[k + 2], 0.f);
            x3 = fmaxf(v.w * s_scale[k + 3] + s_shift[k + 3], 0.f);
        } else {
            x0 = v.x; x1 = v.y; x2 = v.z; x3 = v.w;
        }
        Hs[r][k + 0] = x0;
        Hs[r][k + 1] = x1;
        Hs[r][k + 2] = x2;
        Hs[r][k + 3] = x3;
    }
    __syncthreads();

    const int c     = tid & 127;        // output column (in both matrices)
    const int rbase = (tid >> 7) * 16;  // row group: 0 or 16
    const float* WcolS = Wself  + c;
    const float* WcolN = Wneigh + c;

    unsigned long long accS[16], accN[16];
#pragma unroll
    for (int r = 0; r < 16; r++) { accS[r] = 0ULL; accN[r] = 0ULL; }

#pragma unroll 1
    for (int k = 0; k < DD; k += 8) {
        unsigned long long wsp[4], wnp[4];
#pragma unroll
        for (int j = 0; j < 4; j++) {
            float s0 = __ldg(&WcolS[(k + 2 * j + 0) * DD]);
            float s1 = __ldg(&WcolS[(k + 2 * j + 1) * DD]);
            float n0 = __ldg(&WcolN[(k + 2 * j + 0) * DD]);
            float n1 = __ldg(&WcolN[(k + 2 * j + 1) * DD]);
            wsp[j] = pack2(s0, s1);
            wnp[j] = pack2(n0, n1);
        }
#pragma unroll
        for (int r = 0; r < 16; r++) {
            const ulonglong2* hp = (const ulonglong2*)&Hs[rbase + r][k];
            ulonglong2 a = hp[0];   // (k,k+1),(k+2,k+3)
            ulonglong2 b = hp[1];   // (k+4,k+5),(k+6,k+7)
            fma2(accS[r], a.x, wsp[0]);
            fma2(accN[r], a.x, wnp[0]);
            fma2(accS[r], a.y, wsp[1]);
            fma2(accN[r], a.y, wnp[1]);
            fma2(accS[r], b.x, wsp[2]);
            fma2(accN[r], b.x, wnp[2]);
            fma2(accS[r], b.y, wsp[3]);
            fma2(accN[r], b.y, wnp[3]);
        }
    }

    const float bval = __ldg(&bias[c]);
#pragma unroll
    for (int r = 0; r < 16; r++) {
        int rr = rbase + r;
        if (rr < nrows) {
            size_t rowoff = (size_t)(row0 + rr) * DD;
            S[rowoff + c] = unpack_sum(accS[r]) + bval;
            P[rowoff + c] = unpack_sum(accN[r]);
        }
    }
}

// ---------------- pull-style aggregation: out = S + mean_neigh(P) -----------
__global__ __launch_bounds__(256)
void k_agg(const float* __restrict__ S, const float* __restrict__ P,
           const int* __restrict__ csr, const int* __restrict__ rowptr,
           float* __restrict__ out) {
    int warp = (blockIdx.x * blockDim.x + threadIdx.x) >> 5;
    int lane = threadIdx.x & 31;
    if (warp >= N_NODES) return;

    int beg = rowptr[warp];
    int end = rowptr[warp + 1];

    float4 acc = make_float4(0.f, 0.f, 0.f, 0.f);
    int e = beg;
#pragma unroll 1
    for (; e + 3 < end; e += 4) {
        int s0 = __ldg(&csr[e]);
        int s1 = __ldg(&csr[e + 1]);
        int s2 = __ldg(&csr[e + 2]);
        int s3 = __ldg(&csr[e + 3]);
        float4 p0 = *(const float4*)(P + (size_t)s0 * DD + lane * 4);
        float4 p1 = *(const float4*)(P + (size_t)s1 * DD + lane * 4);
        float4 p2 = *(const float4*)(P + (size_t)s2 * DD + lane * 4);
        float4 p3 = *(const float4*)(P + (size_t)s3 * DD + lane * 4);
        acc.x += (p0.x + p1.x) + (p2.x + p3.x);
        acc.y += (p0.y + p1.y) + (p2.y + p3.y);
        acc.z += (p0.z + p1.z) + (p2.z + p3.z);
        acc.w += (p0.w + p1.w) + (p2.w + p3.w);
    }
#pragma unroll 1
    for (; e < end; e++) {
        int s0 = __ldg(&csr[e]);
        float4 p0 = *(const float4*)(P + (size_t)s0 * DD + lane * 4);
        acc.x += p0.x; acc.y += p0.y; acc.z += p0.z; acc.w += p0.w;
    }

    float inv = 1.0f / fmaxf((float)(end - beg), 1.0f);
    float4 s4 = *(const float4*)(S + (size_t)warp * DD + lane * 4);
    float4 o;
    o.x = s4.x + acc.x * inv;
    o.y = s4.y + acc.y * inv;
    o.z = s4.z + acc.z * inv;
    o.w = s4.w + acc.w * inv;
    *(float4*)(out + (size_t)warp * DD + lane * 4) = o;
}

// ---------------- BN statistics (column sum / sumsq) ------------------------
__global__ __launch_bounds__(128)
void k_bnstats(const float* __restrict__ H, float* __restrict__ colstats) {
    int c = threadIdx.x;   // 128 threads, one column each
    float s = 0.f, ss = 0.f;
    for (int r = blockIdx.x; r < N_NODES; r += gridDim.x) {
        float v = H[(size_t)r * DD + c];
        s  += v;
        ss += v * v;
    }
    atomicAdd(&colstats[c], s);
    atomicAdd(&colstats[DD + c], ss);
}

// ---------------- launch ----------------------------------------------------
extern "C" void kernel_launch(void* const* d_in, const int* in_sizes, int n_in,
                              void* d_out, int out_size) {
    const float* x       = (const float*)d_in[0];
    const int*   src     = (const int*)d_in[1];
    const int*   dst     = (const int*)d_in[2];
    const float* Wself0  = (const float*)d_in[3];
    const float* Wneigh0 = (const float*)d_in[4];
    const float* b0      = (const float*)d_in[5];
    const float* Wself1  = (const float*)d_in[6];
    const float* Wneigh1 = (const float*)d_in[7];
    const float* b1      = (const float*)d_in[8];
    const float* Wself2  = (const float*)d_in[9];
    const float* Wneigh2 = (const float*)d_in[10];
    const float* b2      = (const float*)d_in[11];
    const float* gamma0  = (const float*)d_in[12];
    const float* beta0   = (const float*)d_in[13];
    const float* gamma1  = (const float*)d_in[14];
    const float* beta1   = (const float*)d_in[15];
    float* out = (float*)d_out;

    float *pS, *pP, *pH, *pstats;
    int *pdeg, *prowptr, *pcursor, *pcsr, *pbsum;
    cudaGetSymbolAddress((void**)&pS, g_S);
    cudaGetSymbolAddress((void**)&pP, g_P);
    cudaGetSymbolAddress((void**)&pH, g_H);
    cudaGetSymbolAddress((void**)&pstats, g_colstats);
    cudaGetSymbolAddress((void**)&pdeg, g_deg);
    cudaGetSymbolAddress((void**)&prowptr, g_rowptr);
    cudaGetSymbolAddress((void**)&pcursor, g_cursor);
    cudaGetSymbolAddress((void**)&pcsr, g_csr);
    cudaGetSymbolAddress((void**)&pbsum, g_bsum);

    const int TPB = 256;
    const int edgeBlocks = (N_EDGES + TPB - 1) / TPB;
    const int gemmBlocks = (N_NODES + RTILE - 1) / RTILE;
    const int aggBlocks  = (N_NODES * 32 + TPB - 1) / TPB;

    // ---- CSR build (shared by all 3 layers) ----
    cudaMemsetAsync(pdeg, 0, N_NODES * sizeof(int));
    k_hist<<<edgeBlocks, TPB>>>(dst, pdeg);
    k_scan_part<<<SCAN_B, SCAN_T>>>(pdeg, prowptr, pbsum);
    k_scan_top<<<1, 128>>>(pbsum);
    k_scan_add<<<SCAN_B, SCAN_T>>>(prowptr, pbsum);
    cudaMemcpyAsync(pcursor, prowptr, N_NODES * sizeof(int),
                    cudaMemcpyDeviceToDevice);
    k_fill<<<edgeBlocks, TPB>>>(src, dst, pcursor, pcsr);

    // ---- layer 0: input x, no BN ----
    k_gemm_dual<<<gemmBlocks, TPB>>>(x, Wself0, Wneigh0, b0,
                                     nullptr, nullptr, nullptr, pS, pP);
    k_agg<<<aggBlocks, TPB>>>(pS, pP, pcsr, prowptr, pH);
    cudaMemsetAsync(pstats, 0, 2 * DD * sizeof(float));
    k_bnstats<<<240, 128>>>(pH, pstats);

    // ---- layer 1: BN(gamma0,beta0)+ReLU fused into GEMM load ----
    k_gemm_dual<<<gemmBlocks, TPB>>>(pH, Wself1, Wneigh1, b1,
                                     pstats, gamma0, beta0, pS, pP);
    k_agg<<<aggBlocks, TPB>>>(pS, pP, pcsr, prowptr, pH);
    cudaMemsetAsync(pstats, 0, 2 * DD * sizeof(float));
    k_bnstats<<<240, 128>>>(pH, pstats);

    // ---- layer 2: BN(gamma1,beta1)+ReLU fused, aggregate into d_out ----
    k_gemm_dual<<<gemmBlocks, TPB>>>(pH, Wself2, Wneigh2, b2,
                                     pstats, gamma1, beta1, pS, pP);
    k_agg<<<aggBlocks, TPB>>>(pS, pP, pcsr, prowptr, out);
}

// round 8
// speedup vs baseline: 1.3674x; 1.0948x over previous
#include <cuda_runtime.h>
#include <cuda_bf16.h>
#include <cstdint>

#define N_NODES 50000
#define N_EDGES 800000
#define DD      128
#define RTILE   32
#define BN_EPS  1e-5f
#define SCAN_T  512
#define SCAN_B  ((N_NODES + SCAN_T - 1) / SCAN_T)   // 98

// ---------------- scratch (device globals; no cudaMalloc allowed) ----------
__device__ float          g_S[(size_t)N_NODES * DD];   // self-path GEMM output (fp32)
__device__ __nv_bfloat16  g_Pb[(size_t)N_NODES * DD];  // neigh-path GEMM output (bf16)
__device__ float          g_H[(size_t)N_NODES * DD];   // layer activations (pre-BN)
__device__ int   g_deg[N_NODES];
__device__ int   g_rowptr[N_NODES + 1];
__device__ int   g_cursor[N_NODES];
__device__ int   g_csr[N_EDGES];
__device__ int   g_bsum[128];
__device__ float g_colstats[2 * DD];            // [0:128) colsum, [128:256) colsumsq

// ---------------- f32x2 helpers (sm_103a packed fp32) ----------------------
__device__ __forceinline__ unsigned long long pack2(float a, float b) {
    unsigned long long r;
    asm("mov.b64 %0, {%1, %2};" : "=l"(r) : "f"(a), "f"(b));
    return r;
}
__device__ __forceinline__ void fma2(unsigned long long& d,
                                     unsigned long long a,
                                     unsigned long long b) {
    asm("fma.rn.f32x2 %0, %1, %2, %0;" : "+l"(d) : "l"(a), "l"(b));
}
__device__ __forceinline__ float unpack_sum(unsigned long long v) {
    float lo, hi;
    asm("mov.b64 {%0, %1}, %2;" : "=f"(lo), "=f"(hi) : "l"(v));
    return lo + hi;
}

// ---------------- CSR build -------------------------------------------------
__global__ void k_hist(const int* __restrict__ dst, int* __restrict__ deg) {
    int e = blockIdx.x * blockDim.x + threadIdx.x;
    if (e < N_EDGES) atomicAdd(&deg[dst[e]], 1);
}

__global__ __launch_bounds__(SCAN_T)
void k_scan_part(const int* __restrict__ deg, int* __restrict__ rowptr,
                 int* __restrict__ bsum) {
    __shared__ int sh[SCAN_T];
    int t = threadIdx.x;
    int i = blockIdx.x * SCAN_T + t;
    int v = (i < N_NODES) ? deg[i] : 0;
    sh[t] = v;
    __syncthreads();
#pragma unroll
    for (int off = 1; off < SCAN_T; off <<= 1) {
        int u = (t >= off) ? sh[t - off] : 0;
        __syncthreads();
        sh[t] += u;
        __syncthreads();
    }
    if (i < N_NODES) rowptr[i + 1] = sh[t];
    if (t == SCAN_T - 1) bsum[blockIdx.x] = sh[t];
    if (i == 0) rowptr[0] = 0;
}

__global__ __launch_bounds__(128)
void k_scan_top(int* __restrict__ bsum) {
    __shared__ int sh[128];
    int t = threadIdx.x;
    int v = (t < SCAN_B) ? bsum[t] : 0;
    sh[t] = v;
    __syncthreads();
#pragma unroll
    for (int off = 1; off < 128; off <<= 1) {
        int u = (t >= off) ? sh[t - off] : 0;
        __syncthreads();
        sh[t] += u;
        __syncthreads();
    }
    if (t < SCAN_B) bsum[t] = sh[t];
}

__global__ __launch_bounds__(SCAN_T)
void k_scan_add(int* __restrict__ rowptr, const int* __restrict__ bsum) {
    int b = blockIdx.x;
    if (b == 0) return;
    int i = b * SCAN_T + threadIdx.x;
    if (i < N_NODES) rowptr[i + 1] += bsum[b - 1];
}

__global__ void k_fill(const int* __restrict__ src, const int* __restrict__ dst,
                       int* __restrict__ cursor, int* __restrict__ csr) {
    int e = blockIdx.x * blockDim.x + threadIdx.x;
    if (e < N_EDGES) {
        int d = dst[e];
        int p = atomicAdd(&cursor[d], 1);
        csr[p] = src[e];
    }
}

// ---------------- fused dual GEMM: S = bn(H)@Wself + b (fp32),
//                                   P = bn(H)@Wneigh (bf16) ------------------
__global__ __launch_bounds__(256, 2)
void k_gemm_dual(const float* __restrict__ H,
                 const float* __restrict__ Wself,
                 const float* __restrict__ Wneigh,
                 const float* __restrict__ bias,
                 const float* __restrict__ colstats,  // null -> no BN/ReLU
                 const float* __restrict__ gamma,
                 const float* __restrict__ beta,
                 float* __restrict__ S,
                 __nv_bfloat16* __restrict__ P) {
    __shared__ float Hs[RTILE][DD];
    __shared__ float s_scale[DD];
    __shared__ float s_shift[DD];

    const int tid = threadIdx.x;
    const int row0 = blockIdx.x * RTILE;
    const bool useBn = (colstats != nullptr);

    if (tid < DD) {
        float scale = 1.0f, shift = 0.0f;
        if (useBn) {
            float m   = colstats[tid] * (1.0f / N_NODES);
            float var = colstats[DD + tid] * (1.0f / N_NODES) - m * m;
            float rs  = rsqrtf(var + BN_EPS);
            scale = rs * gamma[tid];
            shift = beta[tid] - m * scale;
        }
        s_scale[tid] = scale;
        s_shift[tid] = shift;
    }
    __syncthreads();

    int nrows = N_NODES - row0;
    if (nrows > RTILE) nrows = RTILE;

#pragma unroll
    for (int i = 0; i < 4; i++) {
        int f  = tid + i * 256;
        int r  = f >> 5;
        int k4 = f & 31;
        float4 v = make_float4(0.f, 0.f, 0.f, 0.f);
        if (r < nrows)
            v = *(const float4*)(H + (size_t)(row0 + r) * DD + k4 * 4);
        int k = k4 * 4;
        float x0, x1, x2, x3;
        if (useBn) {
            x0 = fmaxf(v.x * s_scale[k + 0] + s_shift[k + 0], 0.f);
            x1 = fmaxf(v.y * s_scale[k + 1] + s_shift[k + 1], 0.f);
            x2 = fmaxf(v.z * s_scale[k + 2] + s_shift[k + 2], 0.f);
            x3 = fmaxf(v.w * s_scale[k + 3] + s_shift[k + 3], 0.f);
        } else {
            x0 = v.x; x1 = v.y; x2 = v.z; x3 = v.w;
        }
        Hs[r][k + 0] = x0;
        Hs[r][k + 1] = x1;
        Hs[r][k + 2] = x2;
        Hs[r][k + 3] = x3;
    }
    __syncthreads();

    const int c     = tid & 127;
    const int rbase = (tid >> 7) * 16;
    const float* WcolS = Wself  + c;
    const float* WcolN = Wneigh + c;

    unsigned long long accS[16], accN[16];
#pragma unroll
    for (int r = 0; r < 16; r++) { accS[r] = 0ULL; accN[r] = 0ULL; }

#pragma unroll 1
    for (int k = 0; k < DD; k += 8) {
        unsigned long long wsp[4], wnp[4];
#pragma unroll
        for (int j = 0; j < 4; j++) {
            float s0 = __ldg(&WcolS[(k + 2 * j + 0) * DD]);
            float s1 = __ldg(&WcolS[(k + 2 * j + 1) * DD]);
            float n0 = __ldg(&WcolN[(k + 2 * j + 0) * DD]);
            float n1 = __ldg(&WcolN[(k + 2 * j + 1) * DD]);
            wsp[j] = pack2(s0, s1);
            wnp[j] = pack2(n0, n1);
        }
#pragma unroll
        for (int r = 0; r < 16; r++) {
            const ulonglong2* hp = (const ulonglong2*)&Hs[rbase + r][k];
            ulonglong2 a = hp[0];
            ulonglong2 b = hp[1];
            fma2(accS[r], a.x, wsp[0]);
            fma2(accN[r], a.x, wnp[0]);
            fma2(accS[r], a.y, wsp[1]);
            fma2(accN[r], a.y, wnp[1]);
            fma2(accS[r], b.x, wsp[2]);
            fma2(accN[r], b.x, wnp[2]);
            fma2(accS[r], b.y, wsp[3]);
            fma2(accN[r], b.y, wnp[3]);
        }
    }

    const float bval = __ldg(&bias[c]);
#pragma unroll
    for (int r = 0; r < 16; r++) {
        int rr = rbase + r;
        if (rr < nrows) {
            size_t rowoff = (size_t)(row0 + rr) * DD;
            S[rowoff + c] = unpack_sum(accS[r]) + bval;
            P[rowoff + c] = __float2bfloat16(unpack_sum(accN[r]));
        }
    }
}

// ---------------- pull aggregation + fused BN stats -------------------------
// out = S + mean_neigh(P); optionally accumulate per-column sum/sumsq of out
// into colstats (for the next layer's BN). One warp per node, 8 nodes/block,
// grid divides exactly (6250*8 = 50000) so __syncthreads is uniform.
__global__ __launch_bounds__(256)
void k_agg(const float* __restrict__ S, const __nv_bfloat16* __restrict__ P,
           const int* __restrict__ csr, const int* __restrict__ rowptr,
           float* __restrict__ out, float* __restrict__ colstats) {
    __shared__ float s_sum[DD];
    __shared__ float s_ssq[DD];

    const int tid  = threadIdx.x;
    const int warp = (blockIdx.x * blockDim.x + tid) >> 5;
    const int lane = tid & 31;

    if (colstats && tid < DD) { s_sum[tid] = 0.f; s_ssq[tid] = 0.f; }
    if (colstats) __syncthreads();

    int beg = rowptr[warp];
    int end = rowptr[warp + 1];

    float4 acc = make_float4(0.f, 0.f, 0.f, 0.f);
    int e = beg;
#pragma unroll 1
    for (; e + 3 < end; e += 4) {
        int s0 = __ldg(&csr[e]);
        int s1 = __ldg(&csr[e + 1]);
        int s2 = __ldg(&csr[e + 2]);
        int s3 = __ldg(&csr[e + 3]);
        uint2 v0 = __ldg((const uint2*)(P + (size_t)s0 * DD) + lane);
        uint2 v1 = __ldg((const uint2*)(P + (size_t)s1 * DD) + lane);
        uint2 v2 = __ldg((const uint2*)(P + (size_t)s2 * DD) + lane);
        uint2 v3 = __ldg((const uint2*)(P + (size_t)s3 * DD) + lane);
        float2 a0 = __bfloat1622float2(*(const __nv_bfloat162*)&v0.x);
        float2 b0 = __bfloat1622float2(*(const __nv_bfloat162*)&v0.y);
        float2 a1 = __bfloat1622float2(*(const __nv_bfloat162*)&v1.x);
        float2 b1 = __bfloat1622float2(*(const __nv_bfloat162*)&v1.y);
        float2 a2 = __bfloat1622float2(*(const __nv_bfloat162*)&v2.x);
        float2 b2 = __bfloat1622float2(*(const __nv_bfloat162*)&v2.y);
        float2 a3 = __bfloat1622float2(*(const __nv_bfloat162*)&v3.x);
        float2 b3 = __bfloat1622float2(*(const __nv_bfloat162*)&v3.y);
        acc.x += (a0.x + a1.x) + (a2.x + a3.x);
        acc.y += (a0.y + a1.y) + (a2.y + a3.y);
        acc.z += (b0.x + b1.x) + (b2.x + b3.x);
        acc.w += (b0.y + b1.y) + (b2.y + b3.y);
    }
#pragma unroll 1
    for (; e < end; e++) {
        int s0 = __ldg(&csr[e]);
        uint2 v0 = __ldg((const uint2*)(P + (size_t)s0 * DD) + lane);
        float2 a0 = __bfloat1622float2(*(const __nv_bfloat162*)&v0.x);
        float2 b0 = __bfloat1622float2(*(const __nv_bfloat162*)&v0.y);
        acc.x += a0.x; acc.y += a0.y; acc.z += b0.x; acc.w += b0.y;
    }

    float inv = 1.0f / fmaxf((float)(end - beg), 1.0f);
    float4 s4 = *(const float4*)(S + (size_t)warp * DD + lane * 4);
    float4 o;
    o.x = s4.x + acc.x * inv;
    o.y = s4.y + acc.y * inv;
    o.z = s4.z + acc.z * inv;
    o.w = s4.w + acc.w * inv;
    *(float4*)(out + (size_t)warp * DD + lane * 4) = o;

    if (colstats) {
        int c0 = lane * 4;
        atomicAdd(&s_sum[c0 + 0], o.x);
        atomicAdd(&s_sum[c0 + 1], o.y);
        atomicAdd(&s_sum[c0 + 2], o.z);
        atomicAdd(&s_sum[c0 + 3], o.w);
        atomicAdd(&s_ssq[c0 + 0], o.x * o.x);
        atomicAdd(&s_ssq[c0 + 1], o.y * o.y);
        atomicAdd(&s_ssq[c0 + 2], o.z * o.z);
        atomicAdd(&s_ssq[c0 + 3], o.w * o.w);
        __syncthreads();
        if (tid < DD) {
            atomicAdd(&colstats[tid],      s_sum[tid]);
            atomicAdd(&colstats[DD + tid], s_ssq[tid]);
        }
    }
}

// ---------------- launch ----------------------------------------------------
extern "C" void kernel_launch(void* const* d_in, const int* in_sizes, int n_in,
                              void* d_out, int out_size) {
    const float* x       = (const float*)d_in[0];
    const int*   src     = (const int*)d_in[1];
    const int*   dst     = (const int*)d_in[2];
    const float* Wself0  = (const float*)d_in[3];
    const float* Wneigh0 = (const float*)d_in[4];
    const float* b0      = (const float*)d_in[5];
    const float* Wself1  = (const float*)d_in[6];
    const float* Wneigh1 = (const float*)d_in[7];
    const float* b1      = (const float*)d_in[8];
    const float* Wself2  = (const float*)d_in[9];
    const float* Wneigh2 = (const float*)d_in[10];
    const float* b2      = (const float*)d_in[11];
    const float* gamma0  = (const float*)d_in[12];
    const float* beta0   = (const float*)d_in[13];
    const float* gamma1  = (const float*)d_in[14];
    const float* beta1   = (const float*)d_in[15];
    float* out = (float*)d_out;

    float *pS, *pH, *pstats;
    __nv_bfloat16* pP;
    int *pdeg, *prowptr, *pcursor, *pcsr, *pbsum;
    cudaGetSymbolAddress((void**)&pS, g_S);
    cudaGetSymbolAddress((void**)&pP, g_Pb);
    cudaGetSymbolAddress((void**)&pH, g_H);
    cudaGetSymbolAddress((void**)&pstats, g_colstats);
    cudaGetSymbolAddress((void**)&pdeg, g_deg);
    cudaGetSymbolAddress((void**)&prowptr, g_rowptr);
    cudaGetSymbolAddress((void**)&pcursor, g_cursor);
    cudaGetSymbolAddress((void**)&pcsr, g_csr);
    cudaGetSymbolAddress((void**)&pbsum, g_bsum);

    const int TPB = 256;
    const int edgeBlocks = (N_EDGES + TPB - 1) / TPB;
    const int gemmBlocks = (N_NODES + RTILE - 1) / RTILE;
    const int aggBlocks  = (N_NODES * 32 + TPB - 1) / TPB;   // 6250, exact

    // ---- CSR build (shared by all 3 layers) ----
    cudaMemsetAsync(pdeg, 0, N_NODES * sizeof(int));
    k_hist<<<edgeBlocks, TPB>>>(dst, pdeg);
    k_scan_part<<<SCAN_B, SCAN_T>>>(pdeg, prowptr, pbsum);
    k_scan_top<<<1, 128>>>(pbsum);
    k_scan_add<<<SCAN_B, SCAN_T>>>(prowptr, pbsum);
    cudaMemcpyAsync(pcursor, prowptr, N_NODES * sizeof(int),
                    cudaMemcpyDeviceToDevice);
    k_fill<<<edgeBlocks, TPB>>>(src, dst, pcursor, pcsr);

    // ---- layer 0: input x, no BN; agg computes stats for BN0 ----
    k_gemm_dual<<<gemmBlocks, TPB>>>(x, Wself0, Wneigh0, b0,
                                     nullptr, nullptr, nullptr, pS, pP);
    cudaMemsetAsync(pstats, 0, 2 * DD * sizeof(float));
    k_agg<<<aggBlocks, TPB>>>(pS, pP, pcsr, prowptr, pH, pstats);

    // ---- layer 1: BN(gamma0,beta0)+ReLU fused into GEMM load ----
    k_gemm_dual<<<gemmBlocks, TPB>>>(pH, Wself1, Wneigh1, b1,
                                     pstats, gamma0, beta0, pS, pP);
    cudaMemsetAsync(pstats, 0, 2 * DD * sizeof(float));
    k_agg<<<aggBlocks, TPB>>>(pS, pP, pcsr, prowptr, pH, pstats);

    // ---- layer 2: BN(gamma1,beta1)+ReLU fused, aggregate into d_out ----
    k_gemm_dual<<<gemmBlocks, TPB>>>(pH, Wself2, Wneigh2, b2,
                                     pstats, gamma1, beta1, pS, pP);
    k_agg<<<aggBlocks, TPB>>>(pS, pP, pcsr, prowptr, out, nullptr);
}